// round 10
// baseline (speedup 1.0000x reference)
#include <cuda_runtime.h>
#include <math.h>
#include <cstdint>

#define B_  64
#define T_  2048
#define I_  128
#define H_  256

#define NG 16      // batch groups
#define NS 8       // hidden slices per group
#define NB 4       // batches per group
#define NU 32      // hidden units per slice
#define THREADS 256

#define WXSTRIDE 132   // %32==4 -> conflict-free LDS.128 weight rows

// ---- SMEM layout (float offsets) ----
#define OFF_WX   0
#define SZ_WX    (3*32*WXSTRIDE)           // 12672
#define OFF_BR   (OFF_WX + SZ_WX)
#define OFF_BZ   (OFF_BR + 32)
#define OFF_BIN  (OFF_BZ + 32)
#define OFF_BHN  (OFF_BIN + 32)
#define OFF_X    (OFF_BHN + 32)            // 2 x [b][128] = 1024
#define OFF_H    (OFF_X + 1024)            // [b][256] = 1024 (warp-private strips)
#define OFF_PX   (OFF_H + 1024)            // 2 x [g][b][chunk8][u] = 6144
#define OFF_PH   (OFF_PX + 6144)           // 2 x [g][b][chunk8][u] = 6144
#define SMEM_FLOATS (OFF_PH + 6144)
#define SMEM_BYTES  (SMEM_FLOATS * 4)      // ~108.5 KB

typedef unsigned long long ull;

// Self-validating h exchange: [grp][parity][b][unit] of packed {tag:32 | h:32}.
// tag = t+1 means "h_t". Cleared by out kernel each launch (graph-replay safe).
#define EXCH_WORDS (NG * 2 * NB * 256)     // 32768 u64 = 256 KB
__device__ ull g_exch[EXCH_WORDS];

__device__ __forceinline__ uint32_t smem_u32(const void* p) {
    uint32_t a;
    asm("{ .reg .u64 t; cvta.to.shared.u64 t, %1; cvt.u32.u64 %0, t; }" : "=r"(a) : "l"(p));
    return a;
}
#define FFMA2(d, a, b) \
    asm volatile("fma.rn.f32x2 %0, %1, %2, %0;" : "+l"(d) : "l"(a), "l"(b))

__device__ __forceinline__ float psum(ull v) {
    unsigned lo, hi;
    asm("mov.b64 {%0,%1}, %2;" : "=r"(lo), "=r"(hi) : "l"(v));
    return __uint_as_float(lo) + __uint_as_float(hi);
}
__device__ __forceinline__ ull packf2(float a, float b) {
    ull w;
    asm("mov.b64 %0, {%1,%2};" : "=l"(w) : "r"(__float_as_uint(a)), "r"(__float_as_uint(b)));
    return w;
}
__device__ __forceinline__ void st_relaxed_u64(ull* p, ull v) {
    asm volatile("st.relaxed.gpu.global.u64 [%0], %1;" :: "l"(p), "l"(v) : "memory");
}
__device__ __forceinline__ ull ld_relaxed_u64(const ull* p) {
    ull v;
    asm volatile("ld.relaxed.gpu.global.u64 %0, [%1];" : "=l"(v) : "l"(p) : "memory");
    return v;
}

__global__ void __launch_bounds__(THREADS, 1)
gru_scan_kernel(const float* __restrict__ x,
                const float* __restrict__ Wih,
                const float* __restrict__ Whh,
                const float* __restrict__ bih,
                const float* __restrict__ bhh,
                float* __restrict__ outbuf)
{
    extern __shared__ float smem[];
    const int tid = threadIdx.x;
    const int cta = blockIdx.x;
    const int grp = cta >> 3;
    const int slc = cta & 7;
    const int b0  = grp * NB;
    const int u0  = slc * NU;
    const uint32_t sbase = smem_u32(smem);

    float* hid = outbuf + (size_t)B_ * T_;   // hiddens [B][T][H]

    const int wid = tid >> 5;
    const int u   = tid & 31;
    const int kw  = wid * 32;                // h K-chunk; == units of producer slice `wid`

    // ---- one-time: W_ih slice into SMEM [g][u][k] (stride WXSTRIDE) ----
    for (int rk = tid; rk < 96 * 128; rk += THREADS) {
        int row = rk >> 7;
        int k   = rk & 127;
        int g   = row >> 5;
        int uu  = row & 31;
        smem[OFF_WX + (g * 32 + uu) * WXSTRIDE + k] =
            Wih[(size_t)(g * 256 + u0 + uu) * I_ + k];
    }
    if (tid < 32) {
        int uu = tid;
        smem[OFF_BR  + uu] = bih[0 * 256 + u0 + uu] + bhh[0 * 256 + u0 + uu];
        smem[OFF_BZ  + uu] = bih[1 * 256 + u0 + uu] + bhh[1 * 256 + u0 + uu];
        smem[OFF_BIN + uu] = bih[2 * 256 + u0 + uu];
        smem[OFF_BHN + uu] = bhh[2 * 256 + u0 + uu];
    }
    // preload x_0 into buffer 0: layout [b][k]
    for (int e = tid; e < 512; e += THREADS) {
        int b = e >> 7, k = e & 127;
        smem[OFF_X + e] = x[((size_t)(b0 + b) * T_ + 0) * I_ + k];
    }

    // ---- one-time: W_hh into REGISTERS ----
    ull wh[48];
    #pragma unroll
    for (int g = 0; g < 3; ++g) {
        const float* row = Whh + (size_t)(g * 256 + u0 + u) * H_ + kw;
        #pragma unroll
        for (int j = 0; j < 16; ++j) {
            float2 v = *reinterpret_cast<const float2*>(row + 2 * j);
            wh[g * 16 + j] = packf2(v.x, v.y);
        }
    }
    __syncthreads();

    // per-lane x-weight row bases (gates)
    const float* wx0 = smem + OFF_WX + (0 * 32 + u) * WXSTRIDE;
    const float* wx1 = smem + OFF_WX + (1 * 32 + u) * WXSTRIDE;
    const float* wx2 = smem + OFF_WX + (2 * 32 + u) * WXSTRIDE;

    float hprev_reg = 0.f;    // combine warps: own previous h (batch=wid, unit=u)

    for (int t = 0; t < T_; ++t) {
        const int p = t & 1;
        const int q = p ^ 1;

        // ---- prefetch x_{t+1} (warps 0-3, one float4/lane) ----
        if (wid < 4 && t + 1 < T_) {
            int b = wid, c = u;
            uint32_t dst = sbase + (OFF_X + q * 512 + b * 128 + c * 4) * 4;
            const float* src = x + ((size_t)(b0 + b) * T_ + (t + 1)) * I_ + c * 4;
            asm volatile("cp.async.cg.shared.global [%0], [%1], 16;" :: "r"(dst), "l"(src));
            asm volatile("cp.async.commit_group;" ::: "memory");
        }

        // ---- x-GEMM: all 8 warps, 16 k each (hides producer publish latency) ----
        {
            ull acc[12];
            #pragma unroll
            for (int i = 0; i < 12; ++i) acc[i] = 0ull;

            const float* xq = smem + OFF_X + p * 512;
            const int kx = wid * 16;
            #pragma unroll
            for (int j = 0; j < 4; ++j) {
                const int k = kx + 4 * j;
                ulonglong2 xv0 = *reinterpret_cast<const ulonglong2*>(xq + 0 * 128 + k);
                ulonglong2 xv1 = *reinterpret_cast<const ulonglong2*>(xq + 1 * 128 + k);
                ulonglong2 xv2 = *reinterpret_cast<const ulonglong2*>(xq + 2 * 128 + k);
                ulonglong2 xv3 = *reinterpret_cast<const ulonglong2*>(xq + 3 * 128 + k);
                ulonglong2 w0 = *reinterpret_cast<const ulonglong2*>(wx0 + k);
                ulonglong2 w1 = *reinterpret_cast<const ulonglong2*>(wx1 + k);
                ulonglong2 w2 = *reinterpret_cast<const ulonglong2*>(wx2 + k);
                FFMA2(acc[0], w0.x, xv0.x); FFMA2(acc[0], w0.y, xv0.y);
                FFMA2(acc[1], w0.x, xv1.x); FFMA2(acc[1], w0.y, xv1.y);
                FFMA2(acc[2], w0.x, xv2.x); FFMA2(acc[2], w0.y, xv2.y);
                FFMA2(acc[3], w0.x, xv3.x); FFMA2(acc[3], w0.y, xv3.y);
                FFMA2(acc[4], w1.x, xv0.x); FFMA2(acc[4], w1.y, xv0.y);
                FFMA2(acc[5], w1.x, xv1.x); FFMA2(acc[5], w1.y, xv1.y);
                FFMA2(acc[6], w1.x, xv2.x); FFMA2(acc[6], w1.y, xv2.y);
                FFMA2(acc[7], w1.x, xv3.x); FFMA2(acc[7], w1.y, xv3.y);
                FFMA2(acc[8], w2.x, xv0.x); FFMA2(acc[8], w2.y, xv0.y);
                FFMA2(acc[9], w2.x, xv1.x); FFMA2(acc[9], w2.y, xv1.y);
                FFMA2(acc[10], w2.x, xv2.x); FFMA2(acc[10], w2.y, xv2.y);
                FFMA2(acc[11], w2.x, xv3.x); FFMA2(acc[11], w2.y, xv3.y);
            }
            float* px = smem + OFF_PX + p * 3072;
            #pragma unroll
            for (int g = 0; g < 3; ++g)
                #pragma unroll
                for (int b = 0; b < 4; ++b)
                    px[((g * 4 + b) * 8 + wid) * 32 + u] = psum(acc[g * 4 + b]);
        }

        // ---- poll own slice chunk + h-GEMM (no CTA barrier on this path) ----
        if (t > 0) {
            // lane u owns unit kw+u for all 4 batches: exactly 4 u64 words
            const ull* ep = g_exch + (size_t)(grp * 2 + ((t - 1) & 1)) * NB * 256 + kw + u;
            const unsigned tgt = (unsigned)t;
            ull v0, v1, v2, v3;
            for (;;) {
                v0 = ld_relaxed_u64(ep + 0 * 256);
                v1 = ld_relaxed_u64(ep + 1 * 256);
                v2 = ld_relaxed_u64(ep + 2 * 256);
                v3 = ld_relaxed_u64(ep + 3 * 256);
                bool ok = (unsigned)(v0 >> 32) == tgt && (unsigned)(v1 >> 32) == tgt &&
                          (unsigned)(v2 >> 32) == tgt && (unsigned)(v3 >> 32) == tgt;
                if (__all_sync(0xffffffffu, ok)) break;
            }
            // stage this warp's private strip of sH (only this warp reads it)
            float* hb = smem + OFF_H;
            hb[0 * 256 + kw + u] = __uint_as_float((unsigned)v0);
            hb[1 * 256 + kw + u] = __uint_as_float((unsigned)v1);
            hb[2 * 256 + kw + u] = __uint_as_float((unsigned)v2);
            hb[3 * 256 + kw + u] = __uint_as_float((unsigned)v3);
            __syncwarp();

            ull acc[12];
            #pragma unroll
            for (int i = 0; i < 12; ++i) acc[i] = 0ull;
            #pragma unroll
            for (int jj = 0; jj < 8; ++jj) {
                const int k = kw + 4 * jj;
                ulonglong2 h0 = *reinterpret_cast<const ulonglong2*>(hb + 0 * 256 + k);
                ulonglong2 h1 = *reinterpret_cast<const ulonglong2*>(hb + 1 * 256 + k);
                ulonglong2 h2 = *reinterpret_cast<const ulonglong2*>(hb + 2 * 256 + k);
                ulonglong2 h3 = *reinterpret_cast<const ulonglong2*>(hb + 3 * 256 + k);
                #pragma unroll
                for (int g = 0; g < 3; ++g) {
                    const ull wa = wh[g * 16 + 2 * jj];
                    const ull wb = wh[g * 16 + 2 * jj + 1];
                    FFMA2(acc[g * 4 + 0], wa, h0.x); FFMA2(acc[g * 4 + 0], wb, h0.y);
                    FFMA2(acc[g * 4 + 1], wa, h1.x); FFMA2(acc[g * 4 + 1], wb, h1.y);
                    FFMA2(acc[g * 4 + 2], wa, h2.x); FFMA2(acc[g * 4 + 2], wb, h2.y);
                    FFMA2(acc[g * 4 + 3], wa, h3.x); FFMA2(acc[g * 4 + 3], wb, h3.y);
                }
            }
            float* ph = smem + OFF_PH + p * 3072;
            #pragma unroll
            for (int g = 0; g < 3; ++g)
                #pragma unroll
                for (int b = 0; b < 4; ++b)
                    ph[((g * 4 + b) * 8 + wid) * 32 + u] = psum(acc[g * 4 + b]);
        }

        if (wid < 4 && t + 1 < T_)
            asm volatile("cp.async.wait_group 0;" ::: "memory");
        __syncthreads();   // single barrier: px/ph visible; x_{t+1} landed

        // ---- combine + publish: warps 0-3 (warp = batch, lane = unit) ----
        if (wid < 4) {
            const int bb = wid, uu = u;
            const float* px = smem + OFF_PX + p * 3072;
            float sx0 = 0.f, sx1 = 0.f, sx2 = 0.f;
            #pragma unroll
            for (int c = 0; c < 8; ++c) {
                sx0 += px[((0 * 4 + bb) * 8 + c) * 32 + uu];
                sx1 += px[((1 * 4 + bb) * 8 + c) * 32 + uu];
                sx2 += px[((2 * 4 + bb) * 8 + c) * 32 + uu];
            }
            float sh0 = 0.f, sh1 = 0.f, sh2 = 0.f;
            if (t > 0) {
                const float* ph = smem + OFF_PH + p * 3072;
                #pragma unroll
                for (int c = 0; c < 8; ++c) {
                    sh0 += ph[((0 * 4 + bb) * 8 + c) * 32 + uu];
                    sh1 += ph[((1 * 4 + bb) * 8 + c) * 32 + uu];
                    sh2 += ph[((2 * 4 + bb) * 8 + c) * 32 + uu];
                }
            }
            const float pre_r = sx0 + sh0 + smem[OFF_BR + uu];
            const float pre_z = sx1 + sh1 + smem[OFF_BZ + uu];
            const float r = __fdividef(1.f, 1.f + __expf(-pre_r));
            const float z = __fdividef(1.f, 1.f + __expf(-pre_z));
            const float v = (sx2 + smem[OFF_BIN + uu]) + r * (sh2 + smem[OFF_BHN + uu]);
            const float nn = 1.f - __fdividef(2.f, __expf(2.f * v) + 1.f);   // tanh(v)
            const float hnew = (1.f - z) * nn + z * hprev_reg;
            hprev_reg = hnew;

            // publish {tag = t+1, h} FIRST (critical inter-CTA event), then hid store
            const ull pk = ((ull)(unsigned)(t + 1) << 32) | (ull)__float_as_uint(hnew);
            st_relaxed_u64(g_exch + (size_t)((grp * 2 + p) * NB + bb) * 256 + u0 + uu, pk);

            hid[((size_t)(b0 + bb) * T_ + t) * H_ + u0 + uu] = hnew;
        }
        // no trailing barrier: parity double-buffering (px, ph, sX) + tag backpressure
    }
}

// outputs[b,t] = hiddens[b,t,:] . W_o + b_o ; clears exchange tags for graph replay
__global__ void gru_out_kernel(const float* __restrict__ Wo,
                               const float* __restrict__ bo,
                               float* __restrict__ outbuf)
{
    if (blockIdx.x < 128)
        g_exch[(size_t)blockIdx.x * 256 + threadIdx.x] = 0ull;

    int gw   = (int)((blockIdx.x * blockDim.x + threadIdx.x) >> 5);
    int lane = threadIdx.x & 31;
    if (gw >= B_ * T_) return;

    const float* hrow = outbuf + (size_t)B_ * T_ + (size_t)gw * H_;
    float s = 0.f;
    #pragma unroll
    for (int c = 0; c < 8; ++c) {
        int k = c * 32 + lane;
        s += hrow[k] * __ldg(&Wo[k]);
    }
    #pragma unroll
    for (int off = 16; off; off >>= 1)
        s += __shfl_xor_sync(0xffffffffu, s, off);
    if (lane == 0) outbuf[gw] = s + __ldg(&bo[0]);
}

extern "C" void kernel_launch(void* const* d_in, const int* in_sizes, int n_in,
                              void* d_out, int out_size)
{
    const float* x   = (const float*)d_in[0];
    const float* Wih = (const float*)d_in[1];
    const float* Whh = (const float*)d_in[2];
    const float* bih = (const float*)d_in[3];
    const float* bhh = (const float*)d_in[4];
    const float* Wo  = (const float*)d_in[5];
    const float* bo  = (const float*)d_in[6];
    float* out = (float*)d_out;

    cudaFuncSetAttribute(gru_scan_kernel,
                         cudaFuncAttributeMaxDynamicSharedMemorySize, SMEM_BYTES);

    gru_scan_kernel<<<NG * NS, THREADS, SMEM_BYTES>>>(x, Wih, Whh, bih, bhh, out);
    gru_out_kernel<<<(B_ * T_ * 32) / 256, 256>>>(Wo, bo, out);
}

// round 12
// speedup vs baseline: 1.0681x; 1.0681x over previous
#include <cuda_runtime.h>
#include <math.h>
#include <cstdint>

#define B_  64
#define T_  2048
#define I_  128
#define H_  256

#define NG 16      // batch groups
#define NS 8       // hidden slices per group
#define NB 4       // batches per group
#define NU 32      // hidden units per slice
#define THREADS 256

#define WXSTRIDE 132   // %32==4 -> conflict-free LDS.128 weight rows

// ---- SMEM layout (float offsets) ----
#define OFF_WX   0
#define SZ_WX    (3*32*WXSTRIDE)           // 12672
#define OFF_BR   (OFF_WX + SZ_WX)
#define OFF_BZ   (OFF_BR + 32)
#define OFF_BIN  (OFF_BZ + 32)
#define OFF_BHN  (OFF_BIN + 32)
#define OFF_X    (OFF_BHN + 32)            // 2 x [b][128] = 1024
#define OFF_H    (OFF_X + 1024)            // [b][256] = 1024 (warp-private k-strips)
#define OFF_PX   (OFF_H + 1024)            // 2 x [g][b][chunk4][u] = 3072
#define OFF_PH   (OFF_PX + 3072)           // 2 x [g][b][chunk8][u] = 6144
#define SMEM_FLOATS (OFF_PH + 6144)
#define SMEM_BYTES  (SMEM_FLOATS * 4)      // ~94 KB

typedef unsigned long long ull;

// Self-validating h exchange: [grp][parity][b][unit] of packed {tag:32 | h:32}.
// tag = t+1 means "h_t". Cleared by out kernel each launch (graph-replay safe).
#define EXCH_WORDS (NG * 2 * NB * 256)     // 32768 u64 = 256 KB
__device__ ull g_exch[EXCH_WORDS];

__device__ __forceinline__ uint32_t smem_u32(const void* p) {
    uint32_t a;
    asm("{ .reg .u64 t; cvta.to.shared.u64 t, %1; cvt.u32.u64 %0, t; }" : "=r"(a) : "l"(p));
    return a;
}
#define FFMA2(d, a, b) \
    asm volatile("fma.rn.f32x2 %0, %1, %2, %0;" : "+l"(d) : "l"(a), "l"(b))

__device__ __forceinline__ float psum(ull v) {
    unsigned lo, hi;
    asm("mov.b64 {%0,%1}, %2;" : "=r"(lo), "=r"(hi) : "l"(v));
    return __uint_as_float(lo) + __uint_as_float(hi);
}
__device__ __forceinline__ ull packf2(float a, float b) {
    ull w;
    asm("mov.b64 %0, {%1,%2};" : "=l"(w) : "r"(__float_as_uint(a)), "r"(__float_as_uint(b)));
    return w;
}
__device__ __forceinline__ void st_relaxed_u64(ull* p, ull v) {
    asm volatile("st.relaxed.gpu.global.u64 [%0], %1;" :: "l"(p), "l"(v) : "memory");
}
__device__ __forceinline__ ull ld_relaxed_u64(const ull* p) {
    ull v;
    asm volatile("ld.relaxed.gpu.global.u64 %0, [%1];" : "=l"(v) : "l"(p) : "memory");
    return v;
}
#define BAR_SYNC(id)   asm volatile("bar.sync %0, 256;"   :: "r"(id) : "memory")
#define BAR_ARRIVE(id) asm volatile("bar.arrive %0, 256;" :: "r"(id) : "memory")

__global__ void __launch_bounds__(THREADS, 1)
gru_scan_kernel(const float* __restrict__ x,
                const float* __restrict__ Wih,
                const float* __restrict__ Whh,
                const float* __restrict__ bih,
                const float* __restrict__ bhh,
                float* __restrict__ outbuf)
{
    extern __shared__ float smem[];
    const int tid = threadIdx.x;
    const int cta = blockIdx.x;
    const int grp = cta >> 3;
    const int slc = cta & 7;
    const int b0  = grp * NB;
    const int u0  = slc * NU;
    const uint32_t sbase = smem_u32(smem);

    float* hid = outbuf + (size_t)B_ * T_;   // hiddens [B][T][H]

    const int wid = tid >> 5;
    const int u   = tid & 31;
    const int kw  = wid * 32;                // h K-chunk; == units of producer slice `wid`

    // ---- one-time: W_ih slice into SMEM [g][u][k] (stride WXSTRIDE) ----
    for (int rk = tid; rk < 96 * 128; rk += THREADS) {
        int row = rk >> 7;
        int k   = rk & 127;
        int g   = row >> 5;
        int uu  = row & 31;
        smem[OFF_WX + (g * 32 + uu) * WXSTRIDE + k] =
            Wih[(size_t)(g * 256 + u0 + uu) * I_ + k];
    }
    if (tid < 32) {
        int uu = tid;
        smem[OFF_BR  + uu] = bih[0 * 256 + u0 + uu] + bhh[0 * 256 + u0 + uu];
        smem[OFF_BZ  + uu] = bih[1 * 256 + u0 + uu] + bhh[1 * 256 + u0 + uu];
        smem[OFF_BIN + uu] = bih[2 * 256 + u0 + uu];
        smem[OFF_BHN + uu] = bhh[2 * 256 + u0 + uu];
    }
    // preload x_0 into buffer 0: layout [b][k]
    for (int e = tid; e < 512; e += THREADS) {
        int b = e >> 7, k = e & 127;
        smem[OFF_X + e] = x[((size_t)(b0 + b) * T_ + 0) * I_ + k];
    }

    // ---- one-time: W_hh into REGISTERS (all 8 warps do h-GEMM) ----
    ull wh[48];
    #pragma unroll
    for (int g = 0; g < 3; ++g) {
        const float* row = Whh + (size_t)(g * 256 + u0 + u) * H_ + kw;
        #pragma unroll
        for (int j = 0; j < 16; ++j) {
            float2 v = *reinterpret_cast<const float2*>(row + 2 * j);
            wh[g * 16 + j] = packf2(v.x, v.y);
        }
    }
    __syncthreads();

    if (wid < 4) {
        // ===================== SLOW LANE: the critical cycle =====================
        float hprev_reg = 0.f;   // own previous h (batch=wid, unit=u)
        const int bb = wid, uu = u;

        for (int t = 0; t < T_; ++t) {
            const int p = t & 1;

            if (t > 0) {
                // ---- poll own producer slice `wid` (lane owns unit kw+u, 4 batches) ----
                const ull* ep = g_exch + (size_t)(grp * 2 + ((t - 1) & 1)) * NB * 256 + kw + u;
                const unsigned tgt = (unsigned)t;
                ull v0, v1, v2, v3;
                for (;;) {
                    v0 = ld_relaxed_u64(ep + 0 * 256);
                    v1 = ld_relaxed_u64(ep + 1 * 256);
                    v2 = ld_relaxed_u64(ep + 2 * 256);
                    v3 = ld_relaxed_u64(ep + 3 * 256);
                    bool ok = (unsigned)(v0 >> 32) == tgt && (unsigned)(v1 >> 32) == tgt &&
                              (unsigned)(v2 >> 32) == tgt && (unsigned)(v3 >> 32) == tgt;
                    if (__all_sync(0xffffffffu, ok)) break;
                }
                float* hb = smem + OFF_H;
                hb[0 * 256 + kw + u] = __uint_as_float((unsigned)v0);
                hb[1 * 256 + kw + u] = __uint_as_float((unsigned)v1);
                hb[2 * 256 + kw + u] = __uint_as_float((unsigned)v2);
                hb[3 * 256 + kw + u] = __uint_as_float((unsigned)v3);
                __syncwarp();

                // ---- h-GEMM chunk `wid` ----
                ull acc[12];
                #pragma unroll
                for (int i = 0; i < 12; ++i) acc[i] = 0ull;
                #pragma unroll
                for (int jj = 0; jj < 8; ++jj) {
                    const int k = kw + 4 * jj;
                    ulonglong2 h0 = *reinterpret_cast<const ulonglong2*>(hb + 0 * 256 + k);
                    ulonglong2 h1 = *reinterpret_cast<const ulonglong2*>(hb + 1 * 256 + k);
                    ulonglong2 h2 = *reinterpret_cast<const ulonglong2*>(hb + 2 * 256 + k);
                    ulonglong2 h3 = *reinterpret_cast<const ulonglong2*>(hb + 3 * 256 + k);
                    #pragma unroll
                    for (int g = 0; g < 3; ++g) {
                        const ull wa = wh[g * 16 + 2 * jj];
                        const ull wb = wh[g * 16 + 2 * jj + 1];
                        FFMA2(acc[g * 4 + 0], wa, h0.x); FFMA2(acc[g * 4 + 0], wb, h0.y);
                        FFMA2(acc[g * 4 + 1], wa, h1.x); FFMA2(acc[g * 4 + 1], wb, h1.y);
                        FFMA2(acc[g * 4 + 2], wa, h2.x); FFMA2(acc[g * 4 + 2], wb, h2.y);
                        FFMA2(acc[g * 4 + 3], wa, h3.x); FFMA2(acc[g * 4 + 3], wb, h3.y);
                    }
                }
                float* ph = smem + OFF_PH + p * 3072;
                #pragma unroll
                for (int g = 0; g < 3; ++g)
                    #pragma unroll
                    for (int b = 0; b < 4; ++b)
                        ph[((g * 4 + b) * 8 + wid) * 32 + u] = psum(acc[g * 4 + b]);
            }

            BAR_SYNC(1 + p);   // fast lane's px/ph(t) already arrived (it never waits here)

            // ---- combine (batch=bb, unit=uu) ----
            const float* px = smem + OFF_PX + p * 1536;
            float sx0 = 0.f, sx1 = 0.f, sx2 = 0.f;
            #pragma unroll
            for (int c = 0; c < 4; ++c) {
                sx0 += px[((0 * 4 + bb) * 4 + c) * 32 + uu];
                sx1 += px[((1 * 4 + bb) * 4 + c) * 32 + uu];
                sx2 += px[((2 * 4 + bb) * 4 + c) * 32 + uu];
            }
            float sh0 = 0.f, sh1 = 0.f, sh2 = 0.f;
            if (t > 0) {
                const float* ph = smem + OFF_PH + p * 3072;
                #pragma unroll
                for (int c = 0; c < 8; ++c) {
                    sh0 += ph[((0 * 4 + bb) * 8 + c) * 32 + uu];
                    sh1 += ph[((1 * 4 + bb) * 8 + c) * 32 + uu];
                    sh2 += ph[((2 * 4 + bb) * 8 + c) * 32 + uu];
                }
            }
            const float pre_r = sx0 + sh0 + smem[OFF_BR + uu];
            const float pre_z = sx1 + sh1 + smem[OFF_BZ + uu];
            const float r = __fdividef(1.f, 1.f + __expf(-pre_r));
            const float z = __fdividef(1.f, 1.f + __expf(-pre_z));
            const float v = (sx2 + smem[OFF_BIN + uu]) + r * (sh2 + smem[OFF_BHN + uu]);
            const float nn = 1.f - __fdividef(2.f, __expf(2.f * v) + 1.f);   // tanh(v)
            const float hnew = (1.f - z) * nn + z * hprev_reg;
            hprev_reg = hnew;

            // publish {tag=t+1, h} first, then hid store
            const ull pk = ((ull)(unsigned)(t + 1) << 32) | (ull)__float_as_uint(hnew);
            st_relaxed_u64(g_exch + (size_t)((grp * 2 + p) * NB + bb) * 256 + u0 + uu, pk);

            hid[((size_t)(b0 + bb) * T_ + t) * H_ + u0 + uu] = hnew;
        }
    } else {
        // ===================== FAST LANE: never waits for slow lane =====================
        const int ch = wid - 4;       // x K-chunk 0..3 (k in [ch*32, ch*32+32))
        const int kx = ch * 32;
        // self-sufficient prefetch coords: lane u -> batch u>>3, 16B slice (u&7)*4
        const int pb = u >> 3;
        const int po = (u & 7) * 4;
        const float* wx0 = smem + OFF_WX + (0 * 32 + u) * WXSTRIDE;
        const float* wx1 = smem + OFF_WX + (1 * 32 + u) * WXSTRIDE;
        const float* wx2 = smem + OFF_WX + (2 * 32 + u) * WXSTRIDE;

        for (int t = 0; t < T_; ++t) {
            const int p = t & 1;
            const int q = p ^ 1;

            // retire previous prefetch (this warp's own chunk resident), issue x(t+1)
            asm volatile("cp.async.wait_group 0;" ::: "memory");
            if (t + 1 < T_) {
                uint32_t dst = sbase + (OFF_X + q * 512 + pb * 128 + kx + po) * 4;
                const float* src = x + ((size_t)(b0 + pb) * T_ + (t + 1)) * I_ + kx + po;
                asm volatile("cp.async.cg.shared.global [%0], [%1], 16;" :: "r"(dst), "l"(src));
                asm volatile("cp.async.commit_group;" ::: "memory");
            }

            // ---- x-GEMM: K-chunk ch (only data this warp itself prefetched) ----
            {
                ull acc[12];
                #pragma unroll
                for (int i = 0; i < 12; ++i) acc[i] = 0ull;
                const float* xq = smem + OFF_X + p * 512;
                #pragma unroll
                for (int j = 0; j < 8; ++j) {
                    const int k = kx + 4 * j;
                    ulonglong2 xv0 = *reinterpret_cast<const ulonglong2*>(xq + 0 * 128 + k);
                    ulonglong2 xv1 = *reinterpret_cast<const ulonglong2*>(xq + 1 * 128 + k);
                    ulonglong2 xv2 = *reinterpret_cast<const ulonglong2*>(xq + 2 * 128 + k);
                    ulonglong2 xv3 = *reinterpret_cast<const ulonglong2*>(xq + 3 * 128 + k);
                    ulonglong2 w0 = *reinterpret_cast<const ulonglong2*>(wx0 + k);
                    ulonglong2 w1 = *reinterpret_cast<const ulonglong2*>(wx1 + k);
                    ulonglong2 w2 = *reinterpret_cast<const ulonglong2*>(wx2 + k);
                    FFMA2(acc[0], w0.x, xv0.x); FFMA2(acc[0], w0.y, xv0.y);
                    FFMA2(acc[1], w0.x, xv1.x); FFMA2(acc[1], w0.y, xv1.y);
                    FFMA2(acc[2], w0.x, xv2.x); FFMA2(acc[2], w0.y, xv2.y);
                    FFMA2(acc[3], w0.x, xv3.x); FFMA2(acc[3], w0.y, xv3.y);
                    FFMA2(acc[4], w1.x, xv0.x); FFMA2(acc[4], w1.y, xv0.y);
                    FFMA2(acc[5], w1.x, xv1.x); FFMA2(acc[5], w1.y, xv1.y);
                    FFMA2(acc[6], w1.x, xv2.x); FFMA2(acc[6], w1.y, xv2.y);
                    FFMA2(acc[7], w1.x, xv3.x); FFMA2(acc[7], w1.y, xv3.y);
                    FFMA2(acc[8], w2.x, xv0.x); FFMA2(acc[8], w2.y, xv0.y);
                    FFMA2(acc[9], w2.x, xv1.x); FFMA2(acc[9], w2.y, xv1.y);
                    FFMA2(acc[10], w2.x, xv2.x); FFMA2(acc[10], w2.y, xv2.y);
                    FFMA2(acc[11], w2.x, xv3.x); FFMA2(acc[11], w2.y, xv3.y);
                }
                float* px = smem + OFF_PX + p * 1536;
                #pragma unroll
                for (int g = 0; g < 3; ++g)
                    #pragma unroll
                    for (int b = 0; b < 4; ++b)
                        px[((g * 4 + b) * 4 + ch) * 32 + u] = psum(acc[g * 4 + b]);
            }

            if (t > 0) {
                // ---- poll own producer slice `wid` + h-GEMM chunk `wid` ----
                const ull* ep = g_exch + (size_t)(grp * 2 + ((t - 1) & 1)) * NB * 256 + kw + u;
                const unsigned tgt = (unsigned)t;
                ull v0, v1, v2, v3;
                for (;;) {
                    v0 = ld_relaxed_u64(ep + 0 * 256);
                    v1 = ld_relaxed_u64(ep + 1 * 256);
                    v2 = ld_relaxed_u64(ep + 2 * 256);
                    v3 = ld_relaxed_u64(ep + 3 * 256);
                    bool ok = (unsigned)(v0 >> 32) == tgt && (unsigned)(v1 >> 32) == tgt &&
                              (unsigned)(v2 >> 32) == tgt && (unsigned)(v3 >> 32) == tgt;
                    if (__all_sync(0xffffffffu, ok)) break;
                }
                float* hb = smem + OFF_H;
                hb[0 * 256 + kw + u] = __uint_as_float((unsigned)v0);
                hb[1 * 256 + kw + u] = __uint_as_float((unsigned)v1);
                hb[2 * 256 + kw + u] = __uint_as_float((unsigned)v2);
                hb[3 * 256 + kw + u] = __uint_as_float((unsigned)v3);
                __syncwarp();

                ull acc[12];
                #pragma unroll
                for (int i = 0; i < 12; ++i) acc[i] = 0ull;
                #pragma unroll
                for (int jj = 0; jj < 8; ++jj) {
                    const int k = kw + 4 * jj;
                    ulonglong2 h0 = *reinterpret_cast<const ulonglong2*>(hb + 0 * 256 + k);
                    ulonglong2 h1 = *reinterpret_cast<const ulonglong2*>(hb + 1 * 256 + k);
                    ulonglong2 h2 = *reinterpret_cast<const ulonglong2*>(hb + 2 * 256 + k);
                    ulonglong2 h3 = *reinterpret_cast<const ulonglong2*>(hb + 3 * 256 + k);
                    #pragma unroll
                    for (int g = 0; g < 3; ++g) {
                        const ull wa = wh[g * 16 + 2 * jj];
                        const ull wb = wh[g * 16 + 2 * jj + 1];
                        FFMA2(acc[g * 4 + 0], wa, h0.x); FFMA2(acc[g * 4 + 0], wb, h0.y);
                        FFMA2(acc[g * 4 + 1], wa, h1.x); FFMA2(acc[g * 4 + 1], wb, h1.y);
                        FFMA2(acc[g * 4 + 2], wa, h2.x); FFMA2(acc[g * 4 + 2], wb, h2.y);
                        FFMA2(acc[g * 4 + 3], wa, h3.x); FFMA2(acc[g * 4 + 3], wb, h3.y);
                    }
                }
                float* ph = smem + OFF_PH + p * 3072;
                #pragma unroll
                for (int g = 0; g < 3; ++g)
                    #pragma unroll
                    for (int b = 0; b < 4; ++b)
                        ph[((g * 4 + b) * 8 + wid) * 32 + u] = psum(acc[g * 4 + b]);
            }

            BAR_ARRIVE(1 + p);   // hand off px/ph(t); run ahead (max skew 1 step)
        }
    }
}

// outputs[b,t] = hiddens[b,t,:] . W_o + b_o ; clears exchange tags for graph replay
__global__ void gru_out_kernel(const float* __restrict__ Wo,
                               const float* __restrict__ bo,
                               float* __restrict__ outbuf)
{
    if (blockIdx.x < 128)
        g_exch[(size_t)blockIdx.x * 256 + threadIdx.x] = 0ull;

    int gw   = (int)((blockIdx.x * blockDim.x + threadIdx.x) >> 5);
    int lane = threadIdx.x & 31;
    if (gw >= B_ * T_) return;

    const float* hrow = outbuf + (size_t)B_ * T_ + (size_t)gw * H_;
    float s = 0.f;
    #pragma unroll
    for (int c = 0; c < 8; ++c) {
        int k = c * 32 + lane;
        s += hrow[k] * __ldg(&Wo[k]);
    }
    #pragma unroll
    for (int off = 16; off; off >>= 1)
        s += __shfl_xor_sync(0xffffffffu, s, off);
    if (lane == 0) outbuf[gw] = s + __ldg(&bo[0]);
}

extern "C" void kernel_launch(void* const* d_in, const int* in_sizes, int n_in,
                              void* d_out, int out_size)
{
    const float* x   = (const float*)d_in[0];
    const float* Wih = (const float*)d_in[1];
    const float* Whh = (const float*)d_in[2];
    const float* bih = (const float*)d_in[3];
    const float* bhh = (const float*)d_in[4];
    const float* Wo  = (const float*)d_in[5];
    const float* bo  = (const float*)d_in[6];
    float* out = (float*)d_out;

    cudaFuncSetAttribute(gru_scan_kernel,
                         cudaFuncAttributeMaxDynamicSharedMemorySize, SMEM_BYTES);

    gru_scan_kernel<<<NG * NS, THREADS, SMEM_BYTES>>>(x, Wih, Whh, bih, bhh, out);
    gru_out_kernel<<<(B_ * T_ * 32) / 256, 256>>>(Wo, bo, out);
}

// round 13
// speedup vs baseline: 1.0896x; 1.0202x over previous
#include <cuda_runtime.h>
#include <math.h>
#include <cstdint>

#define B_  64
#define T_  2048
#define I_  128
#define H_  256

#define NG 16      // batch groups
#define NS 8       // hidden slices per group
#define NB 4       // batches per group
#define NU 32      // hidden units per slice
#define THREADS 256

#define WXSTRIDE 132   // %32==4 -> conflict-free LDS.128 weight rows

// ---- SMEM layout (float offsets) ----
#define OFF_WX   0
#define SZ_WX    (3*32*WXSTRIDE)           // 12672
#define OFF_BR   (OFF_WX + SZ_WX)
#define OFF_BZ   (OFF_BR + 32)
#define OFF_BIN  (OFF_BZ + 32)
#define OFF_BHN  (OFF_BIN + 32)
#define OFF_X    (OFF_BHN + 32)            // 2 x [b][128] = 1024
#define OFF_H    (OFF_X + 1024)            // [b][256] = 1024 (warp-private k-strips)
#define OFF_PX   (OFF_H + 1024)            // 2 x [g][b][chunk4][u] = 3072
#define OFF_PH   (OFF_PX + 3072)           // 2 x [g][b][chunk8][u] = 6144
#define SMEM_FLOATS (OFF_PH + 6144)
#define SMEM_BYTES  (SMEM_FLOATS * 4)      // ~94 KB

typedef unsigned long long ull;

// Self-validating h exchange: [grp][parity][b][unit] of packed {tag:32 | h:32}.
// tag = t+1 means "h_t". Cleared by out kernel each launch (graph-replay safe).
#define EXCH_WORDS (NG * 2 * NB * 256)     // 32768 u64 = 256 KB
__device__ ull g_exch[EXCH_WORDS];

__device__ __forceinline__ uint32_t smem_u32(const void* p) {
    uint32_t a;
    asm("{ .reg .u64 t; cvta.to.shared.u64 t, %1; cvt.u32.u64 %0, t; }" : "=r"(a) : "l"(p));
    return a;
}
#define FFMA2(d, a, b) \
    asm volatile("fma.rn.f32x2 %0, %1, %2, %0;" : "+l"(d) : "l"(a), "l"(b))

__device__ __forceinline__ float psum(ull v) {
    unsigned lo, hi;
    asm("mov.b64 {%0,%1}, %2;" : "=r"(lo), "=r"(hi) : "l"(v));
    return __uint_as_float(lo) + __uint_as_float(hi);
}
__device__ __forceinline__ ull packf2(float a, float b) {
    ull w;
    asm("mov.b64 %0, {%1,%2};" : "=l"(w) : "r"(__float_as_uint(a)), "r"(__float_as_uint(b)));
    return w;
}
__device__ __forceinline__ void st_relaxed_u64(ull* p, ull v) {
    asm volatile("st.relaxed.gpu.global.u64 [%0], %1;" :: "l"(p), "l"(v) : "memory");
}
__device__ __forceinline__ ull ld_relaxed_u64(const ull* p) {
    ull v;
    asm volatile("ld.relaxed.gpu.global.u64 %0, [%1];" : "=l"(v) : "l"(p) : "memory");
    return v;
}
#define BAR_SYNC(id)   asm volatile("bar.sync %0, 256;"   :: "r"(id) : "memory")
#define BAR_ARRIVE(id) asm volatile("bar.arrive %0, 256;" :: "r"(id) : "memory")

__global__ void __launch_bounds__(THREADS, 1)
gru_scan_kernel(const float* __restrict__ x,
                const float* __restrict__ Wih,
                const float* __restrict__ Whh,
                const float* __restrict__ bih,
                const float* __restrict__ bhh,
                float* __restrict__ outbuf)
{
    extern __shared__ float smem[];
    const int tid = threadIdx.x;
    const int cta = blockIdx.x;
    const int grp = cta >> 3;
    const int slc = cta & 7;
    const int b0  = grp * NB;
    const int u0  = slc * NU;
    const uint32_t sbase = smem_u32(smem);

    float* hid = outbuf + (size_t)B_ * T_;   // hiddens [B][T][H]

    const int wid = tid >> 5;
    const int u   = tid & 31;
    const int kw  = wid * 32;                // h K-chunk; == units of producer slice `wid`

    // ---- one-time: W_ih slice into SMEM [g][u][k] (stride WXSTRIDE) ----
    for (int rk = tid; rk < 96 * 128; rk += THREADS) {
        int row = rk >> 7;
        int k   = rk & 127;
        int g   = row >> 5;
        int uu  = row & 31;
        smem[OFF_WX + (g * 32 + uu) * WXSTRIDE + k] =
            Wih[(size_t)(g * 256 + u0 + uu) * I_ + k];
    }
    if (tid < 32) {
        int uu = tid;
        smem[OFF_BR  + uu] = bih[0 * 256 + u0 + uu] + bhh[0 * 256 + u0 + uu];
        smem[OFF_BZ  + uu] = bih[1 * 256 + u0 + uu] + bhh[1 * 256 + u0 + uu];
        smem[OFF_BIN + uu] = bih[2 * 256 + u0 + uu];
        smem[OFF_BHN + uu] = bhh[2 * 256 + u0 + uu];
    }
    // preload x_0 into buffer 0: layout [b][k]
    for (int e = tid; e < 512; e += THREADS) {
        int b = e >> 7, k = e & 127;
        smem[OFF_X + e] = x[((size_t)(b0 + b) * T_ + 0) * I_ + k];
    }

    // ---- one-time: W_hh into REGISTERS (all 8 warps do h-GEMM) ----
    ull wh[48];
    #pragma unroll
    for (int g = 0; g < 3; ++g) {
        const float* row = Whh + (size_t)(g * 256 + u0 + u) * H_ + kw;
        #pragma unroll
        for (int j = 0; j < 16; ++j) {
            float2 v = *reinterpret_cast<const float2*>(row + 2 * j);
            wh[g * 16 + j] = packf2(v.x, v.y);
        }
    }
    __syncthreads();

    if (wid < 4) {
        // ===================== SLOW LANE: the critical cycle =====================
        float hprev_reg = 0.f;   // own previous h (batch=wid, unit=u)
        const int bb = wid, uu = u;

        // prime the consumption barriers (as if px/ph of t=-2, t=-1 were consumed)
        BAR_ARRIVE(3);
        BAR_ARRIVE(4);

        for (int t = 0; t < T_; ++t) {
            const int p = t & 1;

            if (t > 0) {
                // ---- poll own producer slice `wid` (lane owns unit kw+u, 4 batches) ----
                const ull* ep = g_exch + (size_t)(grp * 2 + ((t - 1) & 1)) * NB * 256 + kw + u;
                const unsigned tgt = (unsigned)t;
                ull v0, v1, v2, v3;
                for (;;) {
                    v0 = ld_relaxed_u64(ep + 0 * 256);
                    v1 = ld_relaxed_u64(ep + 1 * 256);
                    v2 = ld_relaxed_u64(ep + 2 * 256);
                    v3 = ld_relaxed_u64(ep + 3 * 256);
                    bool ok = (unsigned)(v0 >> 32) == tgt && (unsigned)(v1 >> 32) == tgt &&
                              (unsigned)(v2 >> 32) == tgt && (unsigned)(v3 >> 32) == tgt;
                    if (__all_sync(0xffffffffu, ok)) break;
                }
                float* hb = smem + OFF_H;
                hb[0 * 256 + kw + u] = __uint_as_float((unsigned)v0);
                hb[1 * 256 + kw + u] = __uint_as_float((unsigned)v1);
                hb[2 * 256 + kw + u] = __uint_as_float((unsigned)v2);
                hb[3 * 256 + kw + u] = __uint_as_float((unsigned)v3);
                __syncwarp();

                // ---- h-GEMM chunk `wid` ----
                ull acc[12];
                #pragma unroll
                for (int i = 0; i < 12; ++i) acc[i] = 0ull;
                #pragma unroll
                for (int jj = 0; jj < 8; ++jj) {
                    const int k = kw + 4 * jj;
                    ulonglong2 h0 = *reinterpret_cast<const ulonglong2*>(hb + 0 * 256 + k);
                    ulonglong2 h1 = *reinterpret_cast<const ulonglong2*>(hb + 1 * 256 + k);
                    ulonglong2 h2 = *reinterpret_cast<const ulonglong2*>(hb + 2 * 256 + k);
                    ulonglong2 h3 = *reinterpret_cast<const ulonglong2*>(hb + 3 * 256 + k);
                    #pragma unroll
                    for (int g = 0; g < 3; ++g) {
                        const ull wa = wh[g * 16 + 2 * jj];
                        const ull wb = wh[g * 16 + 2 * jj + 1];
                        FFMA2(acc[g * 4 + 0], wa, h0.x); FFMA2(acc[g * 4 + 0], wb, h0.y);
                        FFMA2(acc[g * 4 + 1], wa, h1.x); FFMA2(acc[g * 4 + 1], wb, h1.y);
                        FFMA2(acc[g * 4 + 2], wa, h2.x); FFMA2(acc[g * 4 + 2], wb, h2.y);
                        FFMA2(acc[g * 4 + 3], wa, h3.x); FFMA2(acc[g * 4 + 3], wb, h3.y);
                    }
                }
                float* ph = smem + OFF_PH + p * 3072;
                #pragma unroll
                for (int g = 0; g < 3; ++g)
                    #pragma unroll
                    for (int b = 0; b < 4; ++b)
                        ph[((g * 4 + b) * 8 + wid) * 32 + u] = psum(acc[g * 4 + b]);
            }

            BAR_SYNC(1 + p);   // fast lane's px/ph(t) arrived (fast lane never waits here)

            // ---- combine (batch=bb, unit=uu) ----
            const float* px = smem + OFF_PX + p * 1536;
            float sx0 = 0.f, sx1 = 0.f, sx2 = 0.f;
            #pragma unroll
            for (int c = 0; c < 4; ++c) {
                sx0 += px[((0 * 4 + bb) * 4 + c) * 32 + uu];
                sx1 += px[((1 * 4 + bb) * 4 + c) * 32 + uu];
                sx2 += px[((2 * 4 + bb) * 4 + c) * 32 + uu];
            }
            float sh0 = 0.f, sh1 = 0.f, sh2 = 0.f;
            if (t > 0) {
                const float* ph = smem + OFF_PH + p * 3072;
                #pragma unroll
                for (int c = 0; c < 8; ++c) {
                    sh0 += ph[((0 * 4 + bb) * 8 + c) * 32 + uu];
                    sh1 += ph[((1 * 4 + bb) * 8 + c) * 32 + uu];
                    sh2 += ph[((2 * 4 + bb) * 8 + c) * 32 + uu];
                }
            }
            const float pre_r = sx0 + sh0 + smem[OFF_BR + uu];
            const float pre_z = sx1 + sh1 + smem[OFF_BZ + uu];
            const float r = __fdividef(1.f, 1.f + __expf(-pre_r));
            const float z = __fdividef(1.f, 1.f + __expf(-pre_z));
            const float v = (sx2 + smem[OFF_BIN + uu]) + r * (sh2 + smem[OFF_BHN + uu]);
            const float nn = 1.f - __fdividef(2.f, __expf(2.f * v) + 1.f);   // tanh(v)
            const float hnew = (1.f - z) * nn + z * hprev_reg;
            hprev_reg = hnew;

            // publish {tag=t+1, h} first (critical inter-CTA event)
            const ull pk = ((ull)(unsigned)(t + 1) << 32) | (ull)__float_as_uint(hnew);
            st_relaxed_u64(g_exch + (size_t)((grp * 2 + p) * NB + bb) * 256 + u0 + uu, pk);

            // px/ph parity p consumed -> release fast lane's iteration t+2 (non-blocking)
            BAR_ARRIVE(3 + p);

            hid[((size_t)(b0 + bb) * T_ + t) * H_ + u0 + uu] = hnew;
        }
    } else {
        // ===================== FAST LANE: throttled to <2 steps ahead =====================
        const int ch = wid - 4;       // x K-chunk 0..3 (k in [ch*32, ch*32+32))
        const int kx = ch * 32;
        // self-sufficient prefetch coords: lane u -> batch u>>3, 16B slice (u&7)*4
        const int pb = u >> 3;
        const int po = (u & 7) * 4;
        const float* wx0 = smem + OFF_WX + (0 * 32 + u) * WXSTRIDE;
        const float* wx1 = smem + OFF_WX + (1 * 32 + u) * WXSTRIDE;
        const float* wx2 = smem + OFF_WX + (2 * 32 + u) * WXSTRIDE;

        for (int t = 0; t < T_; ++t) {
            const int p = t & 1;
            const int q = p ^ 1;

            // retire previous prefetch (this warp's own chunk resident), issue x(t+1)
            asm volatile("cp.async.wait_group 0;" ::: "memory");
            if (t + 1 < T_) {
                uint32_t dst = sbase + (OFF_X + q * 512 + pb * 128 + kx + po) * 4;
                const float* src = x + ((size_t)(b0 + pb) * T_ + (t + 1)) * I_ + kx + po;
                asm volatile("cp.async.cg.shared.global [%0], [%1], 16;" :: "r"(dst), "l"(src));
                asm volatile("cp.async.commit_group;" ::: "memory");
            }

            // throttle: slow lane must have consumed px/ph parity p (from t-2)
            BAR_SYNC(3 + p);

            // ---- x-GEMM: K-chunk ch (only data this warp itself prefetched) ----
            {
                ull acc[12];
                #pragma unroll
                for (int i = 0; i < 12; ++i) acc[i] = 0ull;
                const float* xq = smem + OFF_X + p * 512;
                #pragma unroll
                for (int j = 0; j < 8; ++j) {
                    const int k = kx + 4 * j;
                    ulonglong2 xv0 = *reinterpret_cast<const ulonglong2*>(xq + 0 * 128 + k);
                    ulonglong2 xv1 = *reinterpret_cast<const ulonglong2*>(xq + 1 * 128 + k);
                    ulonglong2 xv2 = *reinterpret_cast<const ulonglong2*>(xq + 2 * 128 + k);
                    ulonglong2 xv3 = *reinterpret_cast<const ulonglong2*>(xq + 3 * 128 + k);
                    ulonglong2 w0 = *reinterpret_cast<const ulonglong2*>(wx0 + k);
                    ulonglong2 w1 = *reinterpret_cast<const ulonglong2*>(wx1 + k);
                    ulonglong2 w2 = *reinterpret_cast<const ulonglong2*>(wx2 + k);
                    FFMA2(acc[0], w0.x, xv0.x); FFMA2(acc[0], w0.y, xv0.y);
                    FFMA2(acc[1], w0.x, xv1.x); FFMA2(acc[1], w0.y, xv1.y);
                    FFMA2(acc[2], w0.x, xv2.x); FFMA2(acc[2], w0.y, xv2.y);
                    FFMA2(acc[3], w0.x, xv3.x); FFMA2(acc[3], w0.y, xv3.y);
                    FFMA2(acc[4], w1.x, xv0.x); FFMA2(acc[4], w1.y, xv0.y);
                    FFMA2(acc[5], w1.x, xv1.x); FFMA2(acc[5], w1.y, xv1.y);
                    FFMA2(acc[6], w1.x, xv2.x); FFMA2(acc[6], w1.y, xv2.y);
                    FFMA2(acc[7], w1.x, xv3.x); FFMA2(acc[7], w1.y, xv3.y);
                    FFMA2(acc[8], w2.x, xv0.x); FFMA2(acc[8], w2.y, xv0.y);
                    FFMA2(acc[9], w2.x, xv1.x); FFMA2(acc[9], w2.y, xv1.y);
                    FFMA2(acc[10], w2.x, xv2.x); FFMA2(acc[10], w2.y, xv2.y);
                    FFMA2(acc[11], w2.x, xv3.x); FFMA2(acc[11], w2.y, xv3.y);
                }
                float* px = smem + OFF_PX + p * 1536;
                #pragma unroll
                for (int g = 0; g < 3; ++g)
                    #pragma unroll
                    for (int b = 0; b < 4; ++b)
                        px[((g * 4 + b) * 4 + ch) * 32 + u] = psum(acc[g * 4 + b]);
            }

            if (t > 0) {
                // ---- poll own producer slice `wid` + h-GEMM chunk `wid` ----
                const ull* ep = g_exch + (size_t)(grp * 2 + ((t - 1) & 1)) * NB * 256 + kw + u;
                const unsigned tgt = (unsigned)t;
                ull v0, v1, v2, v3;
                for (;;) {
                    v0 = ld_relaxed_u64(ep + 0 * 256);
                    v1 = ld_relaxed_u64(ep + 1 * 256);
                    v2 = ld_relaxed_u64(ep + 2 * 256);
                    v3 = ld_relaxed_u64(ep + 3 * 256);
                    bool ok = (unsigned)(v0 >> 32) == tgt && (unsigned)(v1 >> 32) == tgt &&
                              (unsigned)(v2 >> 32) == tgt && (unsigned)(v3 >> 32) == tgt;
                    if (__all_sync(0xffffffffu, ok)) break;
                }
                float* hb = smem + OFF_H;
                hb[0 * 256 + kw + u] = __uint_as_float((unsigned)v0);
                hb[1 * 256 + kw + u] = __uint_as_float((unsigned)v1);
                hb[2 * 256 + kw + u] = __uint_as_float((unsigned)v2);
                hb[3 * 256 + kw + u] = __uint_as_float((unsigned)v3);
                __syncwarp();

                ull acc[12];
                #pragma unroll
                for (int i = 0; i < 12; ++i) acc[i] = 0ull;
                #pragma unroll
                for (int jj = 0; jj < 8; ++jj) {
                    const int k = kw + 4 * jj;
                    ulonglong2 h0 = *reinterpret_cast<const ulonglong2*>(hb + 0 * 256 + k);
                    ulonglong2 h1 = *reinterpret_cast<const ulonglong2*>(hb + 1 * 256 + k);
                    ulonglong2 h2 = *reinterpret_cast<const ulonglong2*>(hb + 2 * 256 + k);
                    ulonglong2 h3 = *reinterpret_cast<const ulonglong2*>(hb + 3 * 256 + k);
                    #pragma unroll
                    for (int g = 0; g < 3; ++g) {
                        const ull wa = wh[g * 16 + 2 * jj];
                        const ull wb = wh[g * 16 + 2 * jj + 1];
                        FFMA2(acc[g * 4 + 0], wa, h0.x); FFMA2(acc[g * 4 + 0], wb, h0.y);
                        FFMA2(acc[g * 4 + 1], wa, h1.x); FFMA2(acc[g * 4 + 1], wb, h1.y);
                        FFMA2(acc[g * 4 + 2], wa, h2.x); FFMA2(acc[g * 4 + 2], wb, h2.y);
                        FFMA2(acc[g * 4 + 3], wa, h3.x); FFMA2(acc[g * 4 + 3], wb, h3.y);
                    }
                }
                float* ph = smem + OFF_PH + p * 3072;
                #pragma unroll
                for (int g = 0; g < 3; ++g)
                    #pragma unroll
                    for (int b = 0; b < 4; ++b)
                        ph[((g * 4 + b) * 8 + wid) * 32 + u] = psum(acc[g * 4 + b]);
            }

            BAR_ARRIVE(1 + p);   // hand off px/ph(t) to slow lane (non-blocking)
        }
    }
}

// outputs[b,t] = hiddens[b,t,:] . W_o + b_o ; clears exchange tags for graph replay
__global__ void gru_out_kernel(const float* __restrict__ Wo,
                               const float* __restrict__ bo,
                               float* __restrict__ outbuf)
{
    if (blockIdx.x < 128)
        g_exch[(size_t)blockIdx.x * 256 + threadIdx.x] = 0ull;

    int gw   = (int)((blockIdx.x * blockDim.x + threadIdx.x) >> 5);
    int lane = threadIdx.x & 31;
    if (gw >= B_ * T_) return;

    const float* hrow = outbuf + (size_t)B_ * T_ + (size_t)gw * H_;
    float s = 0.f;
    #pragma unroll
    for (int c = 0; c < 8; ++c) {
        int k = c * 32 + lane;
        s += hrow[k] * __ldg(&Wo[k]);
    }
    #pragma unroll
    for (int off = 16; off; off >>= 1)
        s += __shfl_xor_sync(0xffffffffu, s, off);
    if (lane == 0) outbuf[gw] = s + __ldg(&bo[0]);
}

extern "C" void kernel_launch(void* const* d_in, const int* in_sizes, int n_in,
                              void* d_out, int out_size)
{
    const float* x   = (const float*)d_in[0];
    const float* Wih = (const float*)d_in[1];
    const float* Whh = (const float*)d_in[2];
    const float* bih = (const float*)d_in[3];
    const float* bhh = (const float*)d_in[4];
    const float* Wo  = (const float*)d_in[5];
    const float* bo  = (const float*)d_in[6];
    float* out = (float*)d_out;

    cudaFuncSetAttribute(gru_scan_kernel,
                         cudaFuncAttributeMaxDynamicSharedMemorySize, SMEM_BYTES);

    gru_scan_kernel<<<NG * NS, THREADS, SMEM_BYTES>>>(x, Wih, Whh, bih, bhh, out);
    gru_out_kernel<<<(B_ * T_ * 32) / 256, 256>>>(Wo, bo, out);
}